// round 16
// baseline (speedup 1.0000x reference)
#include <cuda_runtime.h>
#include <cuda_bf16.h>
#include <cuda_fp16.h>
#include <cstdint>

typedef unsigned int u32;
#define DEV static __device__ __forceinline__

DEV u32 hpack(float lo, float hi){ __half2 h = __floats2half2_rn(lo, hi); return *(u32*)&h; }
DEV float hres(float a){ return a - __half2float(__float2half(a)); }
DEV u32 s2u(const void* p){ u32 a; asm("{ .reg .u64 t; cvta.to.shared.u64 t, %1; cvt.u32.u64 %0, t; }" : "=r"(a) : "l"(p)); return a; }

DEV void ldsm4(u32* r, u32 a){ asm volatile("ldmatrix.sync.aligned.m8n8.x4.shared.b16 {%0,%1,%2,%3}, [%4];"
  : "=r"(r[0]),"=r"(r[1]),"=r"(r[2]),"=r"(r[3]) : "r"(a)); }
DEV void ldsm2(u32* r, u32 a){ asm volatile("ldmatrix.sync.aligned.m8n8.x2.shared.b16 {%0,%1}, [%2];"
  : "=r"(r[0]),"=r"(r[1]) : "r"(a)); }
DEV void mma16816h(float* c, const u32* a, const u32* b){
  asm volatile("mma.sync.aligned.m16n8k16.row.col.f32.f16.f16.f32 {%0,%1,%2,%3},{%4,%5,%6,%7},{%8,%9},{%0,%1,%2,%3};"
    : "+f"(c[0]),"+f"(c[1]),"+f"(c[2]),"+f"(c[3])
    : "r"(a[0]),"r"(a[1]),"r"(a[2]),"r"(a[3]),"r"(b[0]),"r"(b[1]));
}
DEV void cpasync16(u32 dst, const void* src){
  asm volatile("cp.async.cg.shared.global [%0], [%1], 16;" :: "r"(dst), "l"(src) : "memory");
}
#define CP_COMMIT() asm volatile("cp.async.commit_group;" ::: "memory")
#define CP_WAIT0()  asm volatile("cp.async.wait_group 0;" ::: "memory")

// ---- scratch offsets (floats) ----
#define O_LL0 0ull
#define O_HI0 2359296ull
#define O_LL1 11796480ull
#define O_HI1 12386304ull
#define O_LM0 14745600ull
#define O_LM1 17104896ull
#define O_RC  17694720ull
#define O_WS0 20054016ull
#define O_WB  46596096ull
#define O_AB  46800896ull
#define O_WE  46802944ull
#define O_PAD 46827520ull
#define O_WG  56662016ull
#define O_WS1 56711168ull
#define S_TOT 63346688ull

__device__ __align__(16) float g_scratch[S_TOT];

struct StreamInit {
    cudaStream_t s2; cudaEvent_t evF, evJ;
    StreamInit() {
        cudaStreamCreate(&s2);
        cudaEventCreateWithFlags(&evF, cudaEventDisableTiming);
        cudaEventCreateWithFlags(&evJ, cudaEventDisableTiming);
    }
};
static StreamInit g_si;

DEV float softplus_f(float x){ return fmaxf(x, 0.f) + log1pf(__expf(-fabsf(x))); }

// ---- prep: fp16 conv-weight slabs (single term), A=-exp(A_log), Weff ----
__global__ void prep_k(const float* __restrict__ wt, const float* __restrict__ iwt,
                       const float* __restrict__ A_log, const float* __restrict__ W_x,
                       const float* __restrict__ W_dt, float* __restrict__ base)
{
    int i = blockIdx.x * 256 + threadIdx.x;
    if (i < 102400) {
        int f = i / 51200, r = i % 51200;
        int tap = r / 2048, r3 = r % 2048, oc = r3 >> 5, k2 = r3 & 31;
        const float* filt = f ? iwt : wt;
        float w0 = filt[(oc*64 + 2*k2)*25 + tap];
        float w1 = filt[(oc*64 + 2*k2 + 1)*25 + tap];
        ((u32*)base)[O_WB + i] = hpack(w0, w1);
    }
    if (i < 2048) base[O_AB + i] = -__expf(A_log[i]);
    if (i < 16384) {
        int d = i >> 7, k = i & 127;
        float s = 0.f;
        #pragma unroll
        for (int r = 0; r < 4; r++) s += W_dt[d*4 + r] * W_x[r*128 + k];
        base[O_WE + i] = s;
    }
    if (i < 8192) {
        int j = i >> 7, k = i & 127;
        base[O_WE + (size_t)(128 + j)*128 + k] = (j < 32) ? W_x[(4 + j)*128 + k] : 0.f;
    }
}

// ---- prep2: fp16 GEMM weight slabs: W_in 256x64 | Weff 192x128 | W_out 64x128 ----
__global__ void prep2_k(const float* __restrict__ W_in, const float* __restrict__ W_out,
                        float* __restrict__ base)
{
    int i = blockIdx.x * 256 + threadIdx.x;
    if (i >= 24576) return;
    const float* src; int K, n, k2;
    if (i < 8192)       { n = i >> 5; k2 = i & 31; K = 64;  src = W_in; }
    else if (i < 20480) { int j = i - 8192;  n = j >> 6; k2 = j & 63; K = 128; src = base + O_WE; }
    else                { int j = i - 20480; n = j >> 6; k2 = j & 63; K = 128; src = W_out; }
    float w0 = src[(size_t)n*K + 2*k2], w1 = src[(size_t)n*K + 2*k2 + 1];
    ((u32*)base)[O_WG + i] = hpack(w0, w1);
}

// ---- pad into NHWC fp16 hi/lo planes, 4 px per block ----
template<int MODE>
__global__ void pad_k(const float* __restrict__ in, const float* __restrict__ llB,
                      const float* __restrict__ high, void* __restrict__ PADB, int H, int W)
{
    int ic = threadIdx.x & 63, xp = blockIdx.x*4 + (threadIdx.x >> 6);
    int yp = blockIdx.y, b = blockIdx.z;
    int X = W + 4, xi = xp - 2, yi = yp - 2;
    float v = 0.f;
    if ((unsigned)xi < (unsigned)W && (unsigned)yi < (unsigned)H) {
        if (MODE == 0)      v = in[(((size_t)b*64 + ic)*H + yi)*W + xi];
        else if (MODE == 1) v = in[(((size_t)b*64 + ic)*W + xi)*H + yi];
        else {
            int h2 = H>>1, w2 = W>>1, L2 = h2*w2, s = (yi&1)*2 + (xi&1), hy = yi>>1, hx = xi>>1;
            if (s == 0) {
                v = in[((size_t)b*64 + ic)*L2 + hx*h2 + hy];
                if (llB) v += llB[(((size_t)b*64 + ic)*h2 + hy)*w2 + hx];
            } else v = high[((((size_t)b*64 + ic)*4 + s)*h2 + hy)*w2 + hx];
        }
    }
    __half* PH = (__half*)PADB;
    __half* PL = PH + (size_t)4*(H+4)*X*64;
    size_t idx = (((size_t)b*(H+4) + yp)*X + xp)*64 + ic;
    __half hv = __float2half(v);
    PH[idx] = hv;
    PL[idx] = __float2half(v - __half2float(hv));
}

// ---- warp-MMA fp16 2-term conv: M=128(8rows x 16px), N=64 oc, 25 taps x K=64 ic ----
// R13-exact inner loop (interleaved hi/lo MMA, direct-store epilogue).
// smem: A hi [12][20][128B] @0 (30720), A lo @30720, B @61440: 4 bufs x 8192 (32KB).
#define CSM 94208
__global__ void __launch_bounds__(256, 2) convt_k(
    const void* __restrict__ PADB, const u32* __restrict__ WBu,
    float* __restrict__ outP, float* __restrict__ outLL, int H, int W, int OUTMODE)
{
    extern __shared__ char sm[];
    u32 su = s2u(sm);
    int tid = threadIdx.x, wid = tid >> 5, lane = tid & 31;
    int wm = wid & 3, wn = wid >> 2;
    int b = blockIdx.z, Y0 = blockIdx.y * 8, x0 = blockIdx.x * 16;
    int X = W + 4;

    {
        const char* PB = (const char*)PADB;
        size_t termoff = (size_t)4*(H+4)*X*64*2;
        #pragma unroll
        for (int it = 0; it < 15; it++) {
            int i = it*256 + tid;
            int term = i / 1920, r2 = i % 1920, rid = r2 >> 3, ch = r2 & 7;
            int r = rid / 20, xx = rid % 20;
            u32 dst = su + (u32)term*30720u + (u32)(rid*128 + ((ch ^ (rid & 7))*16));
            const char* src = PB + (size_t)term*termoff
                            + ((((size_t)b*(H+4) + Y0 + r)*X + x0 + xx)*64 + ch*8)*2;
            cpasync16(dst, src);
        }
        CP_COMMIT();
    }

    auto issueBpair = [&](int p) {
        #pragma unroll
        for (int tt = 0; tt < 2; tt++) {
            int tap = 2*p + tt;
            if (tap > 24) break;
            #pragma unroll
            for (int it = 0; it < 2; it++) {
                int u = it*256 + tid, oc = u >> 3, ch = u & 7;
                u32 dst = su + 61440u + (u32)(tap & 3)*8192u
                        + (u32)(oc*128 + ((ch ^ (oc & 7))*16));
                cpasync16(dst, WBu + (size_t)tap*2048 + oc*32 + ch*4);
            }
        }
        CP_COMMIT();
    };
    issueBpair(0);

    int pixrow[2], hi16 = lane >> 4;
    #pragma unroll
    for (int mt = 0; mt < 2; mt++) {
        int pix = wm*32 + mt*16 + (lane & 15);
        pixrow[mt] = (pix >> 4)*20 + (pix & 15);
    }
    u32 bnoff[2]; int b7[2]; int bhalf = (lane >> 3) & 1;
    #pragma unroll
    for (int g2 = 0; g2 < 2; g2++) {
        int boc = wn*32 + g2*16 + ((lane >> 4) << 3) + (lane & 7);
        bnoff[g2] = su + 61440u + (u32)(boc*128);
        b7[g2] = boc & 7;
    }

    float acc[2][4][4];
    #pragma unroll
    for (int mt = 0; mt < 2; mt++)
        #pragma unroll
        for (int nt = 0; nt < 4; nt++)
            #pragma unroll
            for (int q = 0; q < 4; q++) acc[mt][nt][q] = 0.f;

    for (int p = 0; p < 13; p++) {
        CP_WAIT0();
        __syncthreads();
        if (p < 12) issueBpair(p + 1);

        #pragma unroll
        for (int tt = 0; tt < 2; tt++) {
            int tap = 2*p + tt;
            if (tap > 24) break;
            int drow = (tap/5)*20 + (tap%5);
            u32 aaddr[2]; int ar7[2];
            #pragma unroll
            for (int mt = 0; mt < 2; mt++) {
                int rid = pixrow[mt] + drow;
                ar7[mt] = rid & 7;
                aaddr[mt] = su + (u32)(rid*128);
            }
            u32 bbuf = (u32)(tap & 3)*8192u;

            #pragma unroll
            for (int ks = 0; ks < 4; ks++) {
                int cA = ks*2 + hi16, cB = ks*2 + bhalf;
                u32 ah[2][4], al[2][4], bh[8];
                #pragma unroll
                for (int mt = 0; mt < 2; mt++) {
                    u32 sw = (u32)(((cA ^ ar7[mt]))*16);
                    ldsm4(ah[mt], aaddr[mt] + sw);
                    ldsm4(al[mt], aaddr[mt] + 30720u + sw);
                }
                #pragma unroll
                for (int g2 = 0; g2 < 2; g2++) {
                    u32 sw = (u32)(((cB ^ b7[g2]))*16);
                    ldsm4(bh + g2*4, bnoff[g2] + bbuf + sw);
                }
                #pragma unroll
                for (int mt = 0; mt < 2; mt++)
                    #pragma unroll
                    for (int nt = 0; nt < 4; nt++) {
                        mma16816h(acc[mt][nt], ah[mt], bh + nt*2);
                        mma16816h(acc[mt][nt], al[mt], bh + nt*2);
                    }
            }
        }
    }

    int g = lane >> 2, t4 = lane & 3;
    int h2 = H >> 1, w2 = W >> 1, L2 = h2*w2;
    #pragma unroll
    for (int mt = 0; mt < 2; mt++)
        #pragma unroll
        for (int half = 0; half < 2; half++) {
            int m = wm*32 + mt*16 + g + half*8;
            int y = Y0 + (m >> 4), gx = x0 + (m & 15);
            #pragma unroll
            for (int nt = 0; nt < 4; nt++)
                #pragma unroll
                for (int q = 0; q < 2; q++) {
                    int oc = wn*32 + nt*8 + 2*t4 + q;
                    float v = acc[mt][nt][half*2 + q];
                    if (OUTMODE == 0) {
                        outP[(((size_t)b*64 + oc)*H + y)*W + gx] = v;
                    } else {
                        int s = (y & 1)*2 + (gx & 1), hy = y >> 1, hx = gx >> 1;
                        if (s == 0) outLL[((size_t)b*64 + oc)*L2 + hx*h2 + hy] = v;
                        else        outP[((((size_t)b*64 + oc)*4 + s)*h2 + hy)*w2 + hx] = v;
                    }
                }
        }
}

// ---- HMMA fp16 2-term GEMM: C[128m x 64n] = A[.,K] @ W[n,K]^T ----
// AMODE 0: A row-major. AMODE 1: seq-gather. AMODE 2: A=xz with fused dwconv+silu (writes xs).
// AMODE 3: A=ys fused (ys+xs*D)*silu(z).
template<int AMODE, int EPI, int K>
__global__ void __launch_bounds__(256) gemmt_k(const float* __restrict__ A, const u32* __restrict__ WG,
    float* __restrict__ out, const float* __restrict__ bias, int lda, int L, float* __restrict__ ws,
    const float* __restrict__ cw, const float* __restrict__ cb)
{
    extern __shared__ char sm[];
    constexpr int rowB = (K + 8) * 2;
    constexpr u32 sAlo = 128u * rowB, sW = 256u * rowB;
    u32 su = s2u(sm);
    int tid = threadIdx.x, wid = tid >> 5, lane = tid & 31;
    int wm = wid & 3, wn = wid >> 2;
    int m0 = blockIdx.x * 128, n0 = blockIdx.y * 64;
    int b = m0 / L, l0 = m0 % L;
    size_t Mt = (size_t)gridDim.x * 128;

    if (AMODE == 0) {
        #pragma unroll
        for (int it = 0; it < K / 8; it++) {
            int i = it*256 + tid;
            int ml = i / (K / 4), kq = i % (K / 4);
            float4 v = *(const float4*)(A + (size_t)(m0 + ml)*lda + kq*4);
            *(uint2*)(sm + ml*rowB + kq*8) = make_uint2(hpack(v.x, v.y), hpack(v.z, v.w));
            *(uint2*)(sm + sAlo + ml*rowB + kq*8) =
                make_uint2(hpack(hres(v.x), hres(v.y)), hpack(hres(v.z), hres(v.w)));
        }
    } else if (AMODE == 2) {
        // fused depthwise causal conv(k=4)+silu over xz; writes xs and stages A
        #pragma unroll
        for (int it = 0; it < K / 8; it++) {
            int i = it*256 + tid;
            int ml = i >> 5, kq = i & 31;
            int m = m0 + ml, l = l0 + ml;
            float4 c0 = *(const float4*)(cw + (kq*4 + 0)*4);
            float4 c1 = *(const float4*)(cw + (kq*4 + 1)*4);
            float4 c2 = *(const float4*)(cw + (kq*4 + 2)*4);
            float4 c3 = *(const float4*)(cw + (kq*4 + 3)*4);
            float4 bb = *(const float4*)(cb + kq*4);
            float4 a0 = bb;
            #pragma unroll
            for (int j = 0; j < 4; j++) {
                int lj = l - 3 + j;
                if (lj >= 0) {
                    float4 xv = *(const float4*)(A + (size_t)(m - 3 + j)*256 + kq*4);
                    a0.x = fmaf((&c0.x)[j], xv.x, a0.x);
                    a0.y = fmaf((&c1.x)[j], xv.y, a0.y);
                    a0.z = fmaf((&c2.x)[j], xv.z, a0.z);
                    a0.w = fmaf((&c3.x)[j], xv.w, a0.w);
                }
            }
            float4 v;
            v.x = a0.x * __fdividef(1.f, 1.f + __expf(-a0.x));
            v.y = a0.y * __fdividef(1.f, 1.f + __expf(-a0.y));
            v.z = a0.z * __fdividef(1.f, 1.f + __expf(-a0.z));
            v.w = a0.w * __fdividef(1.f, 1.f + __expf(-a0.w));
            *(float4*)(ws + Mt*256 + (size_t)m*128 + kq*4) = v;
            *(uint2*)(sm + ml*rowB + kq*8) = make_uint2(hpack(v.x, v.y), hpack(v.z, v.w));
            *(uint2*)(sm + sAlo + ml*rowB + kq*8) =
                make_uint2(hpack(hres(v.x), hres(v.y)), hpack(hres(v.z), hres(v.w)));
        }
    } else if (AMODE == 3) {
        #pragma unroll
        for (int it = 0; it < K / 8; it++) {
            int i = it*256 + tid;
            int ml = i / (K / 4), kq = i % (K / 4);
            int m = m0 + ml;
            float4 ys = *(const float4*)(A + (size_t)m*128 + kq*4);
            float4 xs = *(const float4*)(ws + Mt*256 + (size_t)m*128 + kq*4);
            float4 zz = *(const float4*)(ws + (size_t)m*256 + 128 + kq*4);
            float4 dd = *(const float4*)(bias + kq*4);
            float4 v;
            v.x = (ys.x + xs.x*dd.x) * (zz.x * __fdividef(1.f, 1.f + __expf(-zz.x)));
            v.y = (ys.y + xs.y*dd.y) * (zz.y * __fdividef(1.f, 1.f + __expf(-zz.y)));
            v.z = (ys.z + xs.z*dd.z) * (zz.z * __fdividef(1.f, 1.f + __expf(-zz.z)));
            v.w = (ys.w + xs.w*dd.w) * (zz.w * __fdividef(1.f, 1.f + __expf(-zz.w)));
            *(uint2*)(sm + ml*rowB + kq*8) = make_uint2(hpack(v.x, v.y), hpack(v.z, v.w));
            *(uint2*)(sm + sAlo + ml*rowB + kq*8) =
                make_uint2(hpack(hres(v.x), hres(v.y)), hpack(hres(v.z), hres(v.w)));
        }
    } else {
        #pragma unroll
        for (int it = 0; it < K / 8; it++) {
            int i = it*256 + tid;
            int k = i >> 5, mq = i & 31;
            float4 v = *(const float4*)(A + ((size_t)b*64 + k)*L + l0 + mq*4);
            float vv[4] = {v.x, v.y, v.z, v.w};
            #pragma unroll
            for (int j = 0; j < 4; j++) {
                int ml = mq*4 + j;
                *(__half*)(sm + ml*rowB + k*2) = __float2half(vv[j]);
                *(__half*)(sm + sAlo + ml*rowB + k*2) = __float2half(hres(vv[j]));
            }
        }
    }
    constexpr int kw4 = K / 8;
    #pragma unroll
    for (int it = 0; it < (64*kw4 + 255) / 256; it++) {
        int i = it*256 + tid;
        if (i < 64*kw4) {
            int n = i / kw4, kq = i % kw4;
            uint4 v = *(const uint4*)(WG + (size_t)(n0 + n)*(K/2) + kq*4);
            *(uint4*)(sm + sW + n*rowB + kq*16) = v;
        }
    }
    __syncthreads();

    u32 abase[2], bbase[4];
    #pragma unroll
    for (int mt = 0; mt < 2; mt++)
        abase[mt] = su + (u32)((wm*32 + mt*16 + (lane & 15))*rowB + (lane >> 4)*16);
    #pragma unroll
    for (int nt = 0; nt < 4; nt++)
        bbase[nt] = su + sW + (u32)((wn*32 + nt*8 + (lane & 7))*rowB + ((lane >> 3) & 1)*16);

    float acc[2][4][4];
    #pragma unroll
    for (int mt = 0; mt < 2; mt++)
        #pragma unroll
        for (int nt = 0; nt < 4; nt++)
            #pragma unroll
            for (int q = 0; q < 4; q++) acc[mt][nt][q] = 0.f;

    #pragma unroll
    for (int ks = 0; ks < K / 16; ks++) {
        u32 ko = (u32)(ks*32);
        u32 ah[2][4], al[2][4], bh[4][2];
        #pragma unroll
        for (int mt = 0; mt < 2; mt++) {
            ldsm4(ah[mt], abase[mt] + ko);
            ldsm4(al[mt], abase[mt] + sAlo + ko);
        }
        #pragma unroll
        for (int nt = 0; nt < 4; nt++) ldsm2(bh[nt], bbase[nt] + ko);
        #pragma unroll
        for (int mt = 0; mt < 2; mt++)
            #pragma unroll
            for (int nt = 0; nt < 4; nt++) {
                mma16816h(acc[mt][nt], ah[mt], bh[nt]);
                mma16816h(acc[mt][nt], al[mt], bh[nt]);
            }
    }

    int g = lane >> 2, t4 = lane & 3;
    #pragma unroll
    for (int mt = 0; mt < 2; mt++)
        #pragma unroll
        for (int half = 0; half < 2; half++) {
            int mloc = wm*32 + mt*16 + g + half*8;
            int m = m0 + mloc;
            #pragma unroll
            for (int nt = 0; nt < 4; nt++)
                #pragma unroll
                for (int q = 0; q < 2; q++) {
                    int n = n0 + wn*32 + nt*8 + 2*t4 + q;
                    float v = acc[mt][nt][half*2 + q];
                    if (EPI == 1) {
                        out[(size_t)m*256 + n] = v;
                    } else if (EPI == 2) {
                        if (n < 128)      ws[Mt*384 + (size_t)m*128 + n] = softplus_f(v + bias[n]);
                        else if (n < 160) ws[Mt*512 + (size_t)m*32 + n - 128] = v;
                    } else {
                        out[((size_t)b*64 + n)*L + l0 + mloc] = v;
                    }
                }
        }
}

__global__ void scan1_k(int L, int NCH, float* __restrict__ ws, const float* __restrict__ Ab)
{
    size_t Mt = (size_t)4 * L;
    const float* dt = ws + Mt*384; const float* xs = ws + Mt*256; const float* bc = ws + Mt*512;
    int t = threadIdx.x, s = t & 15;
    int ch = blockIdx.y, b = blockIdx.z, d = blockIdx.x * 16 + (t >> 4);
    float a = Ab[d*16 + s];
    float h = 0.f, P = 1.f;
    size_t ml = (size_t)b*L + (size_t)ch*128;
    for (int i = 0; i < 128; i++) {
        size_t m = ml + i;
        float dtv = __ldg(dt + m*128 + d);
        float e = __expf(dtv * a);
        h = h*e + dtv*__ldg(xs + m*128 + d)*__ldg(bc + m*32 + s);
        P *= e;
    }
    size_t ix = (((size_t)(b*NCH + ch)*128) + d)*16 + s;
    ws[Mt*672 + ix] = P;
    ws[Mt*688 + ix] = h;
}

__global__ void scan2_k(int L, int NCH, float* __restrict__ ws)
{
    size_t Mt = (size_t)4 * L;
    int g = blockIdx.x * 256 + threadIdx.x;
    int b = g >> 11, ds = g & 2047;
    float carry = 0.f;
    for (int ch = 0; ch < NCH; ch++) {
        size_t ix = ((size_t)(b*NCH + ch))*2048 + ds;
        ws[Mt*704 + ix] = carry;
        carry = carry * ws[Mt*672 + ix] + ws[Mt*688 + ix];
    }
}

__global__ void scan3_k(int L, int NCH, float* __restrict__ ws, const float* __restrict__ Ab)
{
    size_t Mt = (size_t)4 * L;
    const float* dt = ws + Mt*384; const float* xs = ws + Mt*256; const float* bc = ws + Mt*512;
    int t = threadIdx.x, s = t & 15;
    int ch = blockIdx.y, b = blockIdx.z, d = blockIdx.x * 16 + (t >> 4);
    float a = Ab[d*16 + s];
    size_t ix = (((size_t)(b*NCH + ch)*128) + d)*16 + s;
    float h = ws[Mt*704 + ix];
    size_t ml = (size_t)b*L + (size_t)ch*128;
    for (int i = 0; i < 128; i++) {
        size_t m = ml + i;
        float dtv = __ldg(dt + m*128 + d);
        float e = __expf(dtv * a);
        h = h*e + dtv*__ldg(xs + m*128 + d)*__ldg(bc + m*32 + s);
        float part = h * __ldg(bc + m*32 + 16 + s);
        part += __shfl_xor_sync(0xffffffffu, part, 8);
        part += __shfl_xor_sync(0xffffffffu, part, 4);
        part += __shfl_xor_sync(0xffffffffu, part, 2);
        part += __shfl_xor_sync(0xffffffffu, part, 1);
        if (s == 0) ws[Mt*544 + m*128 + d] = part;
    }
}

extern "C" void kernel_launch(void* const* d_in, const int* in_sizes, int n_in,
                              void* d_out, int out_size)
{
    const float* x      = (const float*)d_in[0];
    const float* wt     = (const float*)d_in[1];
    const float* iwt    = (const float*)d_in[2];
    const float* W_in   = (const float*)d_in[3];
    const float* conv_w = (const float*)d_in[4];
    const float* conv_b = (const float*)d_in[5];
    const float* W_x    = (const float*)d_in[6];
    const float* W_dt   = (const float*)d_in[7];
    const float* b_dt   = (const float*)d_in[8];
    const float* A_log  = (const float*)d_in[9];
    const float* Dp     = (const float*)d_in[10];
    const float* W_out  = (const float*)d_in[11];
    (void)in_sizes; (void)n_in; (void)out_size;

    float* S = nullptr;
    cudaGetSymbolAddress((void**)&S, g_scratch);
    cudaFuncSetAttribute(convt_k, cudaFuncAttributeMaxDynamicSharedMemorySize, CSM);
    cudaFuncSetAttribute(gemmt_k<1,1,64>,  cudaFuncAttributeMaxDynamicSharedMemorySize, 46080);
    cudaFuncSetAttribute(gemmt_k<2,2,128>, cudaFuncAttributeMaxDynamicSharedMemorySize, 87040);
    cudaFuncSetAttribute(gemmt_k<3,3,128>, cudaFuncAttributeMaxDynamicSharedMemorySize, 87040);
    const u32* WB0 = (const u32*)S + O_WB;
    const u32* WB1 = WB0 + 51200;
    const u32* WG  = (const u32*)S + O_WG;
    const float* Ab = S + O_AB;
    void* PADB = (void*)(S + O_PAD);
    cudaStream_t s2 = g_si.s2;

    prep_k<<<800, 256>>>(wt, iwt, A_log, W_x, W_dt, S);
    prep2_k<<<96, 256>>>(W_in, W_out, S);

    auto mamba = [&](int L, int NCH, const float* llseq, float* llm, float* ws, cudaStream_t st) {
        int M = 4 * L;
        gemmt_k<1,1,64><<<dim3(M/128, 4), 256, 46080, st>>>(llseq, WG, ws, nullptr, 0, L, ws, nullptr, nullptr);
        gemmt_k<2,2,128><<<dim3(M/128, 3), 256, 87040, st>>>(ws, WG + 8192, nullptr, b_dt, 256, L, ws, conv_w, conv_b);
        scan1_k<<<dim3(8, NCH, 4), 256, 0, st>>>(L, NCH, ws, Ab);
        scan2_k<<<32, 256, 0, st>>>(L, NCH, ws);
        scan3_k<<<dim3(8, NCH, 4), 256, 0, st>>>(L, NCH, ws, Ab);
        gemmt_k<3,3,128><<<dim3(M/128, 1), 256, 87040, st>>>(ws + (size_t)M*544, WG + 20480, llm, Dp, 128, L, ws, nullptr, nullptr);
    };

    // level-0 decomposition
    pad_k<0><<<dim3(49,196,4), 256>>>(x, nullptr, nullptr, PADB, 192, 192);
    convt_k<<<dim3(12,24,4), 256, CSM>>>(PADB, WB0, S + O_HI0, S + O_LL0, 192, 192, 1);

    // fork: chain A (default stream) = mamba level-0; chain B (s2) = full level-1 subtree
    cudaEventRecord(g_si.evF, 0);
    cudaStreamWaitEvent(s2, g_si.evF, 0);

    mamba(9216, 72, S + O_LL0, S + O_LM0, S + O_WS0, 0);

    pad_k<1><<<dim3(25,100,4), 256, 0, s2>>>(S + O_LL0, nullptr, nullptr, PADB, 96, 96);
    convt_k<<<dim3(6,12,4), 256, CSM, s2>>>(PADB, WB0, S + O_HI1, S + O_LL1, 96, 96, 1);
    mamba(2304, 18, S + O_LL1, S + O_LM1, S + O_WS1, s2);
    pad_k<2><<<dim3(25,100,4), 256, 0, s2>>>(S + O_LM1, nullptr, S + O_HI1, PADB, 96, 96);
    convt_k<<<dim3(6,12,4), 256, CSM, s2>>>(PADB, WB1, S + O_RC, nullptr, 96, 96, 0);

    // join
    cudaEventRecord(g_si.evJ, s2);
    cudaStreamWaitEvent(0, g_si.evJ, 0);

    pad_k<2><<<dim3(49,196,4), 256>>>(S + O_LM0, S + O_RC, S + O_HI0, PADB, 192, 192);
    convt_k<<<dim3(12,24,4), 256, CSM>>>(PADB, WB1, (float*)d_out, nullptr, 192, 192, 0);
}

// round 17
// speedup vs baseline: 1.0241x; 1.0241x over previous
#include <cuda_runtime.h>
#include <cuda_bf16.h>
#include <cuda_fp16.h>
#include <cstdint>

typedef unsigned int u32;
#define DEV static __device__ __forceinline__

DEV u32 hpack(float lo, float hi){ __half2 h = __floats2half2_rn(lo, hi); return *(u32*)&h; }
DEV float hres(float a){ return a - __half2float(__float2half(a)); }
DEV u32 s2u(const void* p){ u32 a; asm("{ .reg .u64 t; cvta.to.shared.u64 t, %1; cvt.u32.u64 %0, t; }" : "=r"(a) : "l"(p)); return a; }

DEV void ldsm4(u32* r, u32 a){ asm volatile("ldmatrix.sync.aligned.m8n8.x4.shared.b16 {%0,%1,%2,%3}, [%4];"
  : "=r"(r[0]),"=r"(r[1]),"=r"(r[2]),"=r"(r[3]) : "r"(a)); }
DEV void ldsm2(u32* r, u32 a){ asm volatile("ldmatrix.sync.aligned.m8n8.x2.shared.b16 {%0,%1}, [%2];"
  : "=r"(r[0]),"=r"(r[1]) : "r"(a)); }
DEV void mma16816h(float* c, const u32* a, const u32* b){
  asm volatile("mma.sync.aligned.m16n8k16.row.col.f32.f16.f16.f32 {%0,%1,%2,%3},{%4,%5,%6,%7},{%8,%9},{%0,%1,%2,%3};"
    : "+f"(c[0]),"+f"(c[1]),"+f"(c[2]),"+f"(c[3])
    : "r"(a[0]),"r"(a[1]),"r"(a[2]),"r"(a[3]),"r"(b[0]),"r"(b[1]));
}
DEV void cpasync16(u32 dst, const void* src){
  asm volatile("cp.async.cg.shared.global [%0], [%1], 16;" :: "r"(dst), "l"(src) : "memory");
}
#define CP_COMMIT() asm volatile("cp.async.commit_group;" ::: "memory")
#define CP_WAIT0()  asm volatile("cp.async.wait_group 0;" ::: "memory")

// ---- scratch offsets (floats) ----
#define O_LL0 0ull
#define O_HI0 2359296ull
#define O_LL1 11796480ull
#define O_HI1 12386304ull
#define O_LM0 14745600ull
#define O_LM1 17104896ull
#define O_RC  17694720ull
#define O_WS0 20054016ull
#define O_WB  46596096ull
#define O_AB  46800896ull
#define O_WE  46802944ull
#define O_PAD 46827520ull
#define O_WG  56662016ull
#define O_WS1 56711168ull
#define S_TOT 63346688ull

__device__ __align__(16) float g_scratch[S_TOT];

struct StreamInit {
    cudaStream_t s2; cudaEvent_t evF, evJ;
    StreamInit() {
        cudaStreamCreate(&s2);
        cudaEventCreateWithFlags(&evF, cudaEventDisableTiming);
        cudaEventCreateWithFlags(&evJ, cudaEventDisableTiming);
    }
};
static StreamInit g_si;

DEV float softplus_f(float x){ return fmaxf(x, 0.f) + log1pf(__expf(-fabsf(x))); }

// ---- prep: fp16 conv-weight slabs (single term), A=-exp(A_log), Weff ----
__global__ void prep_k(const float* __restrict__ wt, const float* __restrict__ iwt,
                       const float* __restrict__ A_log, const float* __restrict__ W_x,
                       const float* __restrict__ W_dt, float* __restrict__ base)
{
    int i = blockIdx.x * 256 + threadIdx.x;
    if (i < 102400) {
        int f = i / 51200, r = i % 51200;
        int tap = r / 2048, r3 = r % 2048, oc = r3 >> 5, k2 = r3 & 31;
        const float* filt = f ? iwt : wt;
        float w0 = filt[(oc*64 + 2*k2)*25 + tap];
        float w1 = filt[(oc*64 + 2*k2 + 1)*25 + tap];
        ((u32*)base)[O_WB + i] = hpack(w0, w1);
    }
    if (i < 2048) base[O_AB + i] = -__expf(A_log[i]);
    if (i < 16384) {
        int d = i >> 7, k = i & 127;
        float s = 0.f;
        #pragma unroll
        for (int r = 0; r < 4; r++) s += W_dt[d*4 + r] * W_x[r*128 + k];
        base[O_WE + i] = s;
    }
    if (i < 8192) {
        int j = i >> 7, k = i & 127;
        base[O_WE + (size_t)(128 + j)*128 + k] = (j < 32) ? W_x[(4 + j)*128 + k] : 0.f;
    }
}

// ---- prep2: fp16 GEMM weight slabs: W_in 256x64 | Weff 192x128 | W_out 64x128 ----
__global__ void prep2_k(const float* __restrict__ W_in, const float* __restrict__ W_out,
                        float* __restrict__ base)
{
    int i = blockIdx.x * 256 + threadIdx.x;
    if (i >= 24576) return;
    const float* src; int K, n, k2;
    if (i < 8192)       { n = i >> 5; k2 = i & 31; K = 64;  src = W_in; }
    else if (i < 20480) { int j = i - 8192;  n = j >> 6; k2 = j & 63; K = 128; src = base + O_WE; }
    else                { int j = i - 20480; n = j >> 6; k2 = j & 63; K = 128; src = W_out; }
    float w0 = src[(size_t)n*K + 2*k2], w1 = src[(size_t)n*K + 2*k2 + 1];
    ((u32*)base)[O_WG + i] = hpack(w0, w1);
}

// ---- pad into NHWC fp16 hi/lo planes, 4 px per block ----
template<int MODE>
__global__ void pad_k(const float* __restrict__ in, const float* __restrict__ llB,
                      const float* __restrict__ high, void* __restrict__ PADB, int H, int W)
{
    int ic = threadIdx.x & 63, xp = blockIdx.x*4 + (threadIdx.x >> 6);
    int yp = blockIdx.y, b = blockIdx.z;
    int X = W + 4, xi = xp - 2, yi = yp - 2;
    float v = 0.f;
    if ((unsigned)xi < (unsigned)W && (unsigned)yi < (unsigned)H) {
        if (MODE == 0)      v = in[(((size_t)b*64 + ic)*H + yi)*W + xi];
        else if (MODE == 1) v = in[(((size_t)b*64 + ic)*W + xi)*H + yi];
        else {
            int h2 = H>>1, w2 = W>>1, L2 = h2*w2, s = (yi&1)*2 + (xi&1), hy = yi>>1, hx = xi>>1;
            if (s == 0) {
                v = in[((size_t)b*64 + ic)*L2 + hx*h2 + hy];
                if (llB) v += llB[(((size_t)b*64 + ic)*h2 + hy)*w2 + hx];
            } else v = high[((((size_t)b*64 + ic)*4 + s)*h2 + hy)*w2 + hx];
        }
    }
    __half* PH = (__half*)PADB;
    __half* PL = PH + (size_t)4*(H+4)*X*64;
    size_t idx = (((size_t)b*(H+4) + yp)*X + xp)*64 + ic;
    __half hv = __float2half(v);
    PH[idx] = hv;
    PL[idx] = __float2half(v - __half2float(hv));
}

// ---- warp-MMA fp16 2-term conv: M=128(8rows x 16px), N=64 oc, 25 taps x K=64 ic ----
// Interleaved hi/lo MMA, direct-store epilogue (best measured variant).
// smem: A hi [12][20][128B] @0 (30720), A lo @30720, B @61440: 4 bufs x 8192 (32KB).
#define CSM 94208
__global__ void __launch_bounds__(256, 2) convt_k(
    const void* __restrict__ PADB, const u32* __restrict__ WBu,
    float* __restrict__ outP, float* __restrict__ outLL, int H, int W, int OUTMODE)
{
    extern __shared__ char sm[];
    u32 su = s2u(sm);
    int tid = threadIdx.x, wid = tid >> 5, lane = tid & 31;
    int wm = wid & 3, wn = wid >> 2;
    int b = blockIdx.z, Y0 = blockIdx.y * 8, x0 = blockIdx.x * 16;
    int X = W + 4;

    {
        const char* PB = (const char*)PADB;
        size_t termoff = (size_t)4*(H+4)*X*64*2;
        #pragma unroll
        for (int it = 0; it < 15; it++) {
            int i = it*256 + tid;
            int term = i / 1920, r2 = i % 1920, rid = r2 >> 3, ch = r2 & 7;
            int r = rid / 20, xx = rid % 20;
            u32 dst = su + (u32)term*30720u + (u32)(rid*128 + ((ch ^ (rid & 7))*16));
            const char* src = PB + (size_t)term*termoff
                            + ((((size_t)b*(H+4) + Y0 + r)*X + x0 + xx)*64 + ch*8)*2;
            cpasync16(dst, src);
        }
        CP_COMMIT();
    }

    auto issueBpair = [&](int p) {
        #pragma unroll
        for (int tt = 0; tt < 2; tt++) {
            int tap = 2*p + tt;
            if (tap > 24) break;
            #pragma unroll
            for (int it = 0; it < 2; it++) {
                int u = it*256 + tid, oc = u >> 3, ch = u & 7;
                u32 dst = su + 61440u + (u32)(tap & 3)*8192u
                        + (u32)(oc*128 + ((ch ^ (oc & 7))*16));
                cpasync16(dst, WBu + (size_t)tap*2048 + oc*32 + ch*4);
            }
        }
        CP_COMMIT();
    };
    issueBpair(0);

    int pixrow[2], hi16 = lane >> 4;
    #pragma unroll
    for (int mt = 0; mt < 2; mt++) {
        int pix = wm*32 + mt*16 + (lane & 15);
        pixrow[mt] = (pix >> 4)*20 + (pix & 15);
    }
    u32 bnoff[2]; int b7[2]; int bhalf = (lane >> 3) & 1;
    #pragma unroll
    for (int g2 = 0; g2 < 2; g2++) {
        int boc = wn*32 + g2*16 + ((lane >> 4) << 3) + (lane & 7);
        bnoff[g2] = su + 61440u + (u32)(boc*128);
        b7[g2] = boc & 7;
    }

    float acc[2][4][4];
    #pragma unroll
    for (int mt = 0; mt < 2; mt++)
        #pragma unroll
        for (int nt = 0; nt < 4; nt++)
            #pragma unroll
            for (int q = 0; q < 4; q++) acc[mt][nt][q] = 0.f;

    for (int p = 0; p < 13; p++) {
        CP_WAIT0();
        __syncthreads();
        if (p < 12) issueBpair(p + 1);

        #pragma unroll
        for (int tt = 0; tt < 2; tt++) {
            int tap = 2*p + tt;
            if (tap > 24) break;
            int drow = (tap/5)*20 + (tap%5);
            u32 aaddr[2]; int ar7[2];
            #pragma unroll
            for (int mt = 0; mt < 2; mt++) {
                int rid = pixrow[mt] + drow;
                ar7[mt] = rid & 7;
                aaddr[mt] = su + (u32)(rid*128);
            }
            u32 bbuf = (u32)(tap & 3)*8192u;

            #pragma unroll
            for (int ks = 0; ks < 4; ks++) {
                int cA = ks*2 + hi16, cB = ks*2 + bhalf;
                u32 ah[2][4], al[2][4], bh[8];
                #pragma unroll
                for (int mt = 0; mt < 2; mt++) {
                    u32 sw = (u32)(((cA ^ ar7[mt]))*16);
                    ldsm4(ah[mt], aaddr[mt] + sw);
                    ldsm4(al[mt], aaddr[mt] + 30720u + sw);
                }
                #pragma unroll
                for (int g2 = 0; g2 < 2; g2++) {
                    u32 sw = (u32)(((cB ^ b7[g2]))*16);
                    ldsm4(bh + g2*4, bnoff[g2] + bbuf + sw);
                }
                #pragma unroll
                for (int mt = 0; mt < 2; mt++)
                    #pragma unroll
                    for (int nt = 0; nt < 4; nt++) {
                        mma16816h(acc[mt][nt], ah[mt], bh + nt*2);
                        mma16816h(acc[mt][nt], al[mt], bh + nt*2);
                    }
            }
        }
    }

    int g = lane >> 2, t4 = lane & 3;
    int h2 = H >> 1, w2 = W >> 1, L2 = h2*w2;
    #pragma unroll
    for (int mt = 0; mt < 2; mt++)
        #pragma unroll
        for (int half = 0; half < 2; half++) {
            int m = wm*32 + mt*16 + g + half*8;
            int y = Y0 + (m >> 4), gx = x0 + (m & 15);
            #pragma unroll
            for (int nt = 0; nt < 4; nt++)
                #pragma unroll
                for (int q = 0; q < 2; q++) {
                    int oc = wn*32 + nt*8 + 2*t4 + q;
                    float v = acc[mt][nt][half*2 + q];
                    if (OUTMODE == 0) {
                        outP[(((size_t)b*64 + oc)*H + y)*W + gx] = v;
                    } else {
                        int s = (y & 1)*2 + (gx & 1), hy = y >> 1, hx = gx >> 1;
                        if (s == 0) outLL[((size_t)b*64 + oc)*L2 + hx*h2 + hy] = v;
                        else        outP[((((size_t)b*64 + oc)*4 + s)*h2 + hy)*w2 + hx] = v;
                    }
                }
        }
}

// ---- HMMA fp16 2-term GEMM: C[128m x 64n] = A[.,K] @ W[n,K]^T ----
// AMODE 0: A row-major. AMODE 1: seq-gather. AMODE 3: A=ys fused (ys+xs*D)*silu(z).
template<int AMODE, int EPI, int K>
__global__ void __launch_bounds__(256) gemmt_k(const float* __restrict__ A, const u32* __restrict__ WG,
    float* __restrict__ out, const float* __restrict__ bias, int lda, int L, float* __restrict__ ws)
{
    extern __shared__ char sm[];
    constexpr int rowB = (K + 8) * 2;
    constexpr u32 sAlo = 128u * rowB, sW = 256u * rowB;
    u32 su = s2u(sm);
    int tid = threadIdx.x, wid = tid >> 5, lane = tid & 31;
    int wm = wid & 3, wn = wid >> 2;
    int m0 = blockIdx.x * 128, n0 = blockIdx.y * 64;
    int b = m0 / L, l0 = m0 % L;
    size_t Mt = (size_t)gridDim.x * 128;

    if (AMODE == 0) {
        #pragma unroll
        for (int it = 0; it < K / 8; it++) {
            int i = it*256 + tid;
            int ml = i / (K / 4), kq = i % (K / 4);
            float4 v = *(const float4*)(A + (size_t)(m0 + ml)*lda + kq*4);
            *(uint2*)(sm + ml*rowB + kq*8) = make_uint2(hpack(v.x, v.y), hpack(v.z, v.w));
            *(uint2*)(sm + sAlo + ml*rowB + kq*8) =
                make_uint2(hpack(hres(v.x), hres(v.y)), hpack(hres(v.z), hres(v.w)));
        }
    } else if (AMODE == 3) {
        #pragma unroll
        for (int it = 0; it < K / 8; it++) {
            int i = it*256 + tid;
            int ml = i / (K / 4), kq = i % (K / 4);
            int m = m0 + ml;
            float4 ys = *(const float4*)(A + (size_t)m*128 + kq*4);
            float4 xs = *(const float4*)(ws + Mt*256 + (size_t)m*128 + kq*4);
            float4 zz = *(const float4*)(ws + (size_t)m*256 + 128 + kq*4);
            float4 dd = *(const float4*)(bias + kq*4);
            float4 v;
            v.x = (ys.x + xs.x*dd.x) * (zz.x * __fdividef(1.f, 1.f + __expf(-zz.x)));
            v.y = (ys.y + xs.y*dd.y) * (zz.y * __fdividef(1.f, 1.f + __expf(-zz.y)));
            v.z = (ys.z + xs.z*dd.z) * (zz.z * __fdividef(1.f, 1.f + __expf(-zz.z)));
            v.w = (ys.w + xs.w*dd.w) * (zz.w * __fdividef(1.f, 1.f + __expf(-zz.w)));
            *(uint2*)(sm + ml*rowB + kq*8) = make_uint2(hpack(v.x, v.y), hpack(v.z, v.w));
            *(uint2*)(sm + sAlo + ml*rowB + kq*8) =
                make_uint2(hpack(hres(v.x), hres(v.y)), hpack(hres(v.z), hres(v.w)));
        }
    } else {
        #pragma unroll
        for (int it = 0; it < K / 8; it++) {
            int i = it*256 + tid;
            int k = i >> 5, mq = i & 31;
            float4 v = *(const float4*)(A + ((size_t)b*64 + k)*L + l0 + mq*4);
            float vv[4] = {v.x, v.y, v.z, v.w};
            #pragma unroll
            for (int j = 0; j < 4; j++) {
                int ml = mq*4 + j;
                *(__half*)(sm + ml*rowB + k*2) = __float2half(vv[j]);
                *(__half*)(sm + sAlo + ml*rowB + k*2) = __float2half(hres(vv[j]));
            }
        }
    }
    constexpr int kw4 = K / 8;
    #pragma unroll
    for (int it = 0; it < (64*kw4 + 255) / 256; it++) {
        int i = it*256 + tid;
        if (i < 64*kw4) {
            int n = i / kw4, kq = i % kw4;
            uint4 v = *(const uint4*)(WG + (size_t)(n0 + n)*(K/2) + kq*4);
            *(uint4*)(sm + sW + n*rowB + kq*16) = v;
        }
    }
    __syncthreads();

    u32 abase[2], bbase[4];
    #pragma unroll
    for (int mt = 0; mt < 2; mt++)
        abase[mt] = su + (u32)((wm*32 + mt*16 + (lane & 15))*rowB + (lane >> 4)*16);
    #pragma unroll
    for (int nt = 0; nt < 4; nt++)
        bbase[nt] = su + sW + (u32)((wn*32 + nt*8 + (lane & 7))*rowB + ((lane >> 3) & 1)*16);

    float acc[2][4][4];
    #pragma unroll
    for (int mt = 0; mt < 2; mt++)
        #pragma unroll
        for (int nt = 0; nt < 4; nt++)
            #pragma unroll
            for (int q = 0; q < 4; q++) acc[mt][nt][q] = 0.f;

    #pragma unroll
    for (int ks = 0; ks < K / 16; ks++) {
        u32 ko = (u32)(ks*32);
        u32 ah[2][4], al[2][4], bh[4][2];
        #pragma unroll
        for (int mt = 0; mt < 2; mt++) {
            ldsm4(ah[mt], abase[mt] + ko);
            ldsm4(al[mt], abase[mt] + sAlo + ko);
        }
        #pragma unroll
        for (int nt = 0; nt < 4; nt++) ldsm2(bh[nt], bbase[nt] + ko);
        #pragma unroll
        for (int mt = 0; mt < 2; mt++)
            #pragma unroll
            for (int nt = 0; nt < 4; nt++) {
                mma16816h(acc[mt][nt], ah[mt], bh[nt]);
                mma16816h(acc[mt][nt], al[mt], bh[nt]);
            }
    }

    int g = lane >> 2, t4 = lane & 3;
    #pragma unroll
    for (int mt = 0; mt < 2; mt++)
        #pragma unroll
        for (int half = 0; half < 2; half++) {
            int mloc = wm*32 + mt*16 + g + half*8;
            int m = m0 + mloc;
            #pragma unroll
            for (int nt = 0; nt < 4; nt++)
                #pragma unroll
                for (int q = 0; q < 2; q++) {
                    int n = n0 + wn*32 + nt*8 + 2*t4 + q;
                    float v = acc[mt][nt][half*2 + q];
                    if (EPI == 1) {
                        out[(size_t)m*256 + n] = v;
                    } else if (EPI == 2) {
                        if (n < 128)      ws[Mt*384 + (size_t)m*128 + n] = softplus_f(v + bias[n]);
                        else if (n < 160) ws[Mt*512 + (size_t)m*32 + n - 128] = v;
                    } else {
                        out[((size_t)b*64 + n)*L + l0 + mloc] = v;
                    }
                }
        }
}

__global__ void dwconv_k(const float* __restrict__ cw, const float* __restrict__ cb, int L, float* __restrict__ ws)
{
    size_t Mt = (size_t)gridDim.x * 2;
    size_t g = (size_t)blockIdx.x * 256 + threadIdx.x;
    int d = (int)(g & 127);
    size_t m = g >> 7;
    int l = (int)(m % (size_t)L);
    float acc = cb[d];
    #pragma unroll
    for (int j = 0; j < 4; j++) {
        int lj = l - 3 + j;
        if (lj >= 0) acc = fmaf(cw[d*4 + j], ws[(m - 3 + j)*256 + d], acc);
    }
    ws[Mt*256 + g] = acc * __fdividef(1.f, 1.f + __expf(-acc));
}

__global__ void scan1_k(int L, int NCH, float* __restrict__ ws, const float* __restrict__ Ab)
{
    size_t Mt = (size_t)4 * L;
    const float* dt = ws + Mt*384; const float* xs = ws + Mt*256; const float* bc = ws + Mt*512;
    int t = threadIdx.x, s = t & 15;
    int ch = blockIdx.y, b = blockIdx.z, d = blockIdx.x * 16 + (t >> 4);
    float a = Ab[d*16 + s];
    float h = 0.f, P = 1.f;
    size_t ml = (size_t)b*L + (size_t)ch*128;
    for (int i = 0; i < 128; i++) {
        size_t m = ml + i;
        float dtv = __ldg(dt + m*128 + d);
        float e = __expf(dtv * a);
        h = h*e + dtv*__ldg(xs + m*128 + d)*__ldg(bc + m*32 + s);
        P *= e;
    }
    size_t ix = (((size_t)(b*NCH + ch)*128) + d)*16 + s;
    ws[Mt*672 + ix] = P;
    ws[Mt*688 + ix] = h;
}

__global__ void scan2_k(int L, int NCH, float* __restrict__ ws)
{
    size_t Mt = (size_t)4 * L;
    int g = blockIdx.x * 256 + threadIdx.x;
    int b = g >> 11, ds = g & 2047;
    float carry = 0.f;
    for (int ch = 0; ch < NCH; ch++) {
        size_t ix = ((size_t)(b*NCH + ch))*2048 + ds;
        ws[Mt*704 + ix] = carry;
        carry = carry * ws[Mt*672 + ix] + ws[Mt*688 + ix];
    }
}

__global__ void scan3_k(int L, int NCH, float* __restrict__ ws, const float* __restrict__ Ab)
{
    size_t Mt = (size_t)4 * L;
    const float* dt = ws + Mt*384; const float* xs = ws + Mt*256; const float* bc = ws + Mt*512;
    int t = threadIdx.x, s = t & 15;
    int ch = blockIdx.y, b = blockIdx.z, d = blockIdx.x * 16 + (t >> 4);
    float a = Ab[d*16 + s];
    size_t ix = (((size_t)(b*NCH + ch)*128) + d)*16 + s;
    float h = ws[Mt*704 + ix];
    size_t ml = (size_t)b*L + (size_t)ch*128;
    for (int i = 0; i < 128; i++) {
        size_t m = ml + i;
        float dtv = __ldg(dt + m*128 + d);
        float e = __expf(dtv * a);
        h = h*e + dtv*__ldg(xs + m*128 + d)*__ldg(bc + m*32 + s);
        float part = h * __ldg(bc + m*32 + 16 + s);
        part += __shfl_xor_sync(0xffffffffu, part, 8);
        part += __shfl_xor_sync(0xffffffffu, part, 4);
        part += __shfl_xor_sync(0xffffffffu, part, 2);
        part += __shfl_xor_sync(0xffffffffu, part, 1);
        if (s == 0) ws[Mt*544 + m*128 + d] = part;
    }
}

extern "C" void kernel_launch(void* const* d_in, const int* in_sizes, int n_in,
                              void* d_out, int out_size)
{
    const float* x      = (const float*)d_in[0];
    const float* wt     = (const float*)d_in[1];
    const float* iwt    = (const float*)d_in[2];
    const float* W_in   = (const float*)d_in[3];
    const float* conv_w = (const float*)d_in[4];
    const float* conv_b = (const float*)d_in[5];
    const float* W_x    = (const float*)d_in[6];
    const float* W_dt   = (const float*)d_in[7];
    const float* b_dt   = (const float*)d_in[8];
    const float* A_log  = (const float*)d_in[9];
    const float* Dp     = (const float*)d_in[10];
    const float* W_out  = (const float*)d_in[11];
    (void)in_sizes; (void)n_in; (void)out_size;

    float* S = nullptr;
    cudaGetSymbolAddress((void**)&S, g_scratch);
    cudaFuncSetAttribute(convt_k, cudaFuncAttributeMaxDynamicSharedMemorySize, CSM);
    cudaFuncSetAttribute(gemmt_k<1,1,64>,  cudaFuncAttributeMaxDynamicSharedMemorySize, 46080);
    cudaFuncSetAttribute(gemmt_k<0,2,128>, cudaFuncAttributeMaxDynamicSharedMemorySize, 87040);
    cudaFuncSetAttribute(gemmt_k<3,3,128>, cudaFuncAttributeMaxDynamicSharedMemorySize, 87040);
    const u32* WB0 = (const u32*)S + O_WB;
    const u32* WB1 = WB0 + 51200;
    const u32* WG  = (const u32*)S + O_WG;
    const float* Ab = S + O_AB;
    void* PADB = (void*)(S + O_PAD);
    cudaStream_t s2 = g_si.s2;

    prep_k<<<800, 256>>>(wt, iwt, A_log, W_x, W_dt, S);
    prep2_k<<<96, 256>>>(W_in, W_out, S);

    auto mamba = [&](int L, int NCH, const float* llseq, float* llm, float* ws, cudaStream_t st) {
        int M = 4 * L;
        gemmt_k<1,1,64><<<dim3(M/128, 4), 256, 46080, st>>>(llseq, WG, ws, nullptr, 0, L, ws);
        dwconv_k<<<(M*128)/256, 256, 0, st>>>(conv_w, conv_b, L, ws);
        gemmt_k<0,2,128><<<dim3(M/128, 3), 256, 87040, st>>>(ws + (size_t)M*256, WG + 8192, nullptr, b_dt, 128, L, ws);
        scan1_k<<<dim3(8, NCH, 4), 256, 0, st>>>(L, NCH, ws, Ab);
        scan2_k<<<32, 256, 0, st>>>(L, NCH, ws);
        scan3_k<<<dim3(8, NCH, 4), 256, 0, st>>>(L, NCH, ws, Ab);
        gemmt_k<3,3,128><<<dim3(M/128, 1), 256, 87040, st>>>(ws + (size_t)M*544, WG + 20480, llm, Dp, 128, L, ws);
    };

    // level-0 decomposition
    pad_k<0><<<dim3(49,196,4), 256>>>(x, nullptr, nullptr, PADB, 192, 192);
    convt_k<<<dim3(12,24,4), 256, CSM>>>(PADB, WB0, S + O_HI0, S + O_LL0, 192, 192, 1);

    // fork: chain A (default stream) = mamba level-0; chain B (s2) = full level-1 subtree
    cudaEventRecord(g_si.evF, 0);
    cudaStreamWaitEvent(s2, g_si.evF, 0);

    mamba(9216, 72, S + O_LL0, S + O_LM0, S + O_WS0, 0);

    pad_k<1><<<dim3(25,100,4), 256, 0, s2>>>(S + O_LL0, nullptr, nullptr, PADB, 96, 96);
    convt_k<<<dim3(6,12,4), 256, CSM, s2>>>(PADB, WB0, S + O_HI1, S + O_LL1, 96, 96, 1);
    mamba(2304, 18, S + O_LL1, S + O_LM1, S + O_WS1, s2);
    pad_k<2><<<dim3(25,100,4), 256, 0, s2>>>(S + O_LM1, nullptr, S + O_HI1, PADB, 96, 96);
    convt_k<<<dim3(6,12,4), 256, CSM, s2>>>(PADB, WB1, S + O_RC, nullptr, 96, 96, 0);

    // join
    cudaEventRecord(g_si.evJ, s2);
    cudaStreamWaitEvent(0, g_si.evJ, 0);

    pad_k<2><<<dim3(49,196,4), 256>>>(S + O_LM0, S + O_RC, S + O_HI0, PADB, 192, 192);
    convt_k<<<dim3(12,24,4), 256, CSM>>>(PADB, WB1, (float*)d_out, nullptr, 192, 192, 0);
}